// round 14
// baseline (speedup 1.0000x reference)
#include <cuda_runtime.h>
#include <cuda_bf16.h>
#include <math.h>

#define NN 100000
#define EE 1600000
#define DD 64
#define CC 2

// Static device scratch (no allocation allowed).
// g_deg is zero at module load and reset to 0 by k_scale every call.
__device__ int2   g_rc[EE];    // packed (row, col) per edge
__device__ int    g_deg[NN];   // in-degree WITHOUT self loop
__device__ float2 g_y0[NN];    // x @ W.T (unscaled)
__device__ float2 g_z0[NN];    // dinv * y0
__device__ float4 g_a1[NN];    // .xy = t1 accum (seeded with self term z0), .z = dinv^2, .w = dinv
__device__ float2 g_t2[NN];    // hop-2 edge-only accumulator (init 0)

// no-return reductions (REDG)
__device__ __forceinline__ void red_add_f2(float2* p, float a, float b) {
    asm volatile("red.global.add.v2.f32 [%0], {%1, %2};"
                 :: "l"(p), "f"(a), "f"(b) : "memory");
}
__device__ __forceinline__ void red_add_1(int* p) {
    asm volatile("red.global.add.s32 [%0], %1;" :: "l"(p), "r"(1) : "memory");
}

// Programmatic Dependent Launch helpers
__device__ __forceinline__ void pdl_sync() {
#if defined(__CUDA_ARCH__) && __CUDA_ARCH__ >= 900
    cudaGridDependencySynchronize();
#endif
}
__device__ __forceinline__ void pdl_trigger() {
#if defined(__CUDA_ARCH__) && __CUDA_ARCH__ >= 900
    cudaTriggerProgrammaticLaunchCompletion();
#endif
}

// ---------------- kernels ----------------

// Fused front end: blocks [0, gc) convert edges + count degree;
// blocks [gc, gc+gw) compute y0 = x @ W.T (16 lanes per node). Independent halves.
__global__ void k_count_mv(const void* __restrict__ edge,
                           const float* __restrict__ x,
                           const float* __restrict__ W,
                           int e, int n, int gc) {
    if ((int)blockIdx.x < gc) {
        // ---- edge conversion + degree count, 4 edges/thread ----
        __shared__ int s_is64;
        if (threadIdx.x < 32) {
            const long long* e64 = (const long long*)edge;
            long long v0 = e64[threadIdx.x];
            long long v1 = e64[threadIdx.x + 32];
            int ok = (v0 >= 0) && (v0 < (long long)n) &&
                     (v1 >= 0) && (v1 < (long long)n);
            unsigned ball = __ballot_sync(0xffffffffu, ok);
            if (threadIdx.x == 0) s_is64 = (ball == 0xffffffffu);
        }
        __syncthreads();
        const int is64 = s_is64;

        int base = (blockIdx.x * blockDim.x + threadIdx.x) * 4;
        if (base < e) {
            int r[4], c[4];
            int m = min(4, e - base);
            if (is64) {
                // int64 ids < n live in the low word; pick .x/.z of int4 loads.
                const int* p = (const int*)edge;
                if (m == 4) {
                    int4 ra = *(const int4*)(p + 2 * base);
                    int4 rb = *(const int4*)(p + 2 * base + 4);
                    int4 ca = *(const int4*)(p + 2 * (e + base));
                    int4 cb = *(const int4*)(p + 2 * (e + base) + 4);
                    r[0]=ra.x; r[1]=ra.z; r[2]=rb.x; r[3]=rb.z;
                    c[0]=ca.x; c[1]=ca.z; c[2]=cb.x; c[3]=cb.z;
                } else {
                    for (int k = 0; k < m; k++) {
                        r[k] = p[2 * (base + k)];
                        c[k] = p[2 * (e + base + k)];
                    }
                }
            } else {
                const int* e32 = (const int*)edge;
                if (m == 4) {
                    int4 rr = *(const int4*)(e32 + base);
                    int4 cc = *(const int4*)(e32 + e + base);
                    r[0]=rr.x; r[1]=rr.y; r[2]=rr.z; r[3]=rr.w;
                    c[0]=cc.x; c[1]=cc.y; c[2]=cc.z; c[3]=cc.w;
                } else {
                    for (int k = 0; k < m; k++) { r[k]=e32[base+k]; c[k]=e32[e+base+k]; }
                }
            }
            #pragma unroll
            for (int k = 0; k < 4; k++) {
                if (k >= m) break;
                int rr = r[k], cc = c[k];
                if ((unsigned)rr >= (unsigned)n || (unsigned)cc >= (unsigned)n) { rr = 0; cc = 0; }
                g_rc[base + k] = make_int2(rr, cc);
                red_add_1(&g_deg[cc]);
            }
        }
        __threadfence();   // order REDs/stores before programmatic trigger
        pdl_trigger();
    } else {
        // ---- matvec: y0 = x @ W.T, 16 lanes per node, float4 loads ----
        __shared__ float4 sW[2 * DD / 4];
        int t = threadIdx.x;
        if (t < 2 * DD / 4) sW[t] = ((const float4*)W)[t];
        __syncthreads();
        int node = (((int)blockIdx.x - gc) * blockDim.x + t) >> 4;
        int l = t & 15;
        if (node < n) {
            float4 xv = ((const float4*)(x + (size_t)node * DD))[l];
            float4 w0 = sW[l];
            float4 w1 = sW[DD / 4 + l];
            float s0 = xv.x * w0.x + xv.y * w0.y + xv.z * w0.z + xv.w * w0.w;
            float s1 = xv.x * w1.x + xv.y * w1.y + xv.z * w1.z + xv.w * w1.w;
            #pragma unroll
            for (int o = 8; o; o >>= 1) {
                s0 += __shfl_xor_sync(0xffffffffu, s0, o);
                s1 += __shfl_xor_sync(0xffffffffu, s1, o);
            }
            if (l == 0) g_y0[node] = make_float2(s0, s1);
        }
        __threadfence();
        pdl_trigger();
    }
}

// scale: d = rsqrt(deg+1); z0 = d*y0; a1 = (z0, d^2, d); t2 = 0; deg -> 0
__global__ void k_scale(int n) {
    pdl_sync();   // wait for k_count_mv's data
    int i = blockIdx.x * blockDim.x + threadIdx.x;
    if (i < n) {
        float d = rsqrtf((float)(g_deg[i] + 1));
        g_deg[i] = 0;
        float2 y = g_y0[i];
        float2 z = make_float2(d * y.x, d * y.y);
        g_z0[i] = z;
        g_a1[i] = make_float4(z.x, z.y, d * d, d);
        g_t2[i] = make_float2(0.f, 0.f);
    }
    __threadfence();
    pdl_trigger();
}

// hop 1 (edges only, 2/thread): a1.xy[c] += z0[r]
__global__ void k_edge1(int e) {
    pdl_sync();   // wait for k_scale's data (transitively k_count_mv)
    int base = (blockIdx.x * blockDim.x + threadIdx.x) * 2;
    if (base < e) {
        if (base + 1 < e) {
            int4 p = *(const int4*)&g_rc[base];   // (r0,c0,r1,c1)
            float2 v0 = __ldg(&g_z0[p.x]);
            float2 v1 = __ldg(&g_z0[p.z]);
            red_add_f2((float2*)&g_a1[p.y], v0.x, v0.y);
            red_add_f2((float2*)&g_a1[p.w], v1.x, v1.y);
        } else {
            int2 rc = g_rc[base];
            float2 v = __ldg(&g_z0[rc.x]);
            red_add_f2((float2*)&g_a1[rc.y], v.x, v.y);
        }
    }
    __threadfence();
    pdl_trigger();
}

// hop 2 (edges only, 2/thread): t2[c] += d2[r]*t1[r]
__global__ void k_edge2(int e) {
    pdl_sync();
    int base = (blockIdx.x * blockDim.x + threadIdx.x) * 2;
    if (base < e) {
        if (base + 1 < e) {
            int4 p = *(const int4*)&g_rc[base];
            float4 a0 = __ldg(&g_a1[p.x]);
            float4 a1v = __ldg(&g_a1[p.z]);
            red_add_f2(&g_t2[p.y], a0.z * a0.x, a0.z * a0.y);
            red_add_f2(&g_t2[p.w], a1v.z * a1v.x, a1v.z * a1v.y);
        } else {
            int2 rc = g_rc[base];
            float4 a = __ldg(&g_a1[rc.x]);
            red_add_f2(&g_t2[rc.y], a.z * a.x, a.z * a.y);
        }
    }
    __threadfence();
    pdl_trigger();
}

// out = log_softmax(dinv * (t2 + d^2 * t1) + b); hop-2 self term folded in.
__global__ void k_out(const float* __restrict__ b, float* __restrict__ out, int n) {
    pdl_sync();
    int i = blockIdx.x * blockDim.x + threadIdx.x;
    if (i >= n) return;
    float4 a = g_a1[i];            // .xy = t1 final, .z = d^2, .w = dinv
    float2 t = g_t2[i];
    float l0 = a.w * (t.x + a.z * a.x) + b[0];
    float l1 = a.w * (t.y + a.z * a.y) + b[1];
    float m = fmaxf(l0, l1);
    float lse = m + logf(expf(l0 - m) + expf(l1 - m));
    *(float2*)(out + 2 * i) = make_float2(l0 - lse, l1 - lse);
}

// ---------------- launch ----------------

template <typename... Args>
static void launch_pdl(void (*kern)(Args...), int grid, int block, Args... args) {
    cudaLaunchConfig_t cfg = {};
    cfg.gridDim = dim3(grid);
    cfg.blockDim = dim3(block);
    cudaLaunchAttribute attr[1];
    attr[0].id = cudaLaunchAttributeProgrammaticStreamSerialization;
    attr[0].val.programmaticStreamSerializationAllowed = 1;
    cfg.attrs = attr;
    cfg.numAttrs = 1;
    cudaLaunchKernelEx(&cfg, kern, args...);
}

extern "C" void kernel_launch(void* const* d_in, const int* in_sizes, int n_in,
                              void* d_out, int out_size) {
    const float* x    = (const float*)d_in[0];
    const void*  edge = d_in[1];
    const float* W    = (const float*)d_in[2];
    const float* b    = (const float*)d_in[3];
    float*       out  = (float*)d_out;

    int n = in_sizes[0] / DD;   // 100000
    int e = in_sizes[1] / 2;    // 1600000

    const int T = 256;
    int gn  = (n + T - 1) / T;
    int gc  = ((e + 3) / 4 + T - 1) / T;
    int ge2 = ((e + 1) / 2 + T - 1) / T;
    int gw  = ((size_t)n * 16 + T - 1) / T;

    // First kernel: plain launch (no upstream dependency).
    k_count_mv<<<gc + gw, T>>>(edge, x, W, e, n, gc);
    // Dependents: PDL so each overlaps its launch/ramp with the producer's drain.
    launch_pdl(k_scale, gn, T, n);
    launch_pdl(k_edge1, ge2, T, e);
    launch_pdl(k_edge2, ge2, T, e);
    launch_pdl(k_out, gn, T, b, out, n);
}

// round 15
// speedup vs baseline: 1.1695x; 1.1695x over previous
#include <cuda_runtime.h>
#include <cuda_bf16.h>
#include <math.h>

#define NN 100000
#define EE 1600000
#define DD 64
#define CC 2

// Static device scratch (no allocation allowed).
// g_deg is zero at module load and reset to 0 by k_scale every call.
__device__ int2   g_rc[EE];    // packed (row, col) per edge
__device__ int    g_deg[NN];   // in-degree WITHOUT self loop
__device__ float2 g_y0[NN];    // x @ W.T (unscaled)
__device__ float2 g_z0[NN];    // dinv * y0
__device__ float4 g_a1[NN];    // .xy = t1 accum (seeded with self term z0), .z = dinv^2, .w = dinv
__device__ float2 g_t2[NN];    // hop-2 edge-only accumulator (init 0)

// no-return reductions (REDG)
__device__ __forceinline__ void red_add_f2(float2* p, float a, float b) {
    asm volatile("red.global.add.v2.f32 [%0], {%1, %2};"
                 :: "l"(p), "f"(a), "f"(b) : "memory");
}
__device__ __forceinline__ void red_add_1(int* p) {
    asm volatile("red.global.add.s32 [%0], %1;" :: "l"(p), "r"(1) : "memory");
}
// streaming store (evict-first): output is write-once, never re-read
__device__ __forceinline__ void st_cs_f2(float2* p, float2 v) {
    asm volatile("st.global.cs.v2.f32 [%0], {%1, %2};"
                 :: "l"(p), "f"(v.x), "f"(v.y) : "memory");
}

// ---------------- kernels ----------------

// Fused front end: blocks [0, gc) convert edges + count degree;
// blocks [gc, gc+gw) compute y0 = x @ W.T (16 lanes per node). Independent halves.
__global__ void k_count_mv(const void* __restrict__ edge,
                           const float* __restrict__ x,
                           const float* __restrict__ W,
                           int e, int n, int gc) {
    if ((int)blockIdx.x < gc) {
        // ---- edge conversion + degree count, 4 edges/thread ----
        __shared__ int s_is64;
        if (threadIdx.x < 32) {
            const long long* e64 = (const long long*)edge;
            long long v0 = e64[threadIdx.x];
            long long v1 = e64[threadIdx.x + 32];
            int ok = (v0 >= 0) && (v0 < (long long)n) &&
                     (v1 >= 0) && (v1 < (long long)n);
            unsigned ball = __ballot_sync(0xffffffffu, ok);
            if (threadIdx.x == 0) s_is64 = (ball == 0xffffffffu);
        }
        __syncthreads();
        const int is64 = s_is64;

        int base = (blockIdx.x * blockDim.x + threadIdx.x) * 4;
        if (base >= e) return;
        int r[4], c[4];
        int m = min(4, e - base);
        if (is64) {
            // int64 ids < n live in the low word; pick .x/.z of int4 loads.
            const int* p = (const int*)edge;
            if (m == 4) {
                int4 ra = *(const int4*)(p + 2 * base);
                int4 rb = *(const int4*)(p + 2 * base + 4);
                int4 ca = *(const int4*)(p + 2 * (e + base));
                int4 cb = *(const int4*)(p + 2 * (e + base) + 4);
                r[0]=ra.x; r[1]=ra.z; r[2]=rb.x; r[3]=rb.z;
                c[0]=ca.x; c[1]=ca.z; c[2]=cb.x; c[3]=cb.z;
            } else {
                for (int k = 0; k < m; k++) {
                    r[k] = p[2 * (base + k)];
                    c[k] = p[2 * (e + base + k)];
                }
            }
        } else {
            const int* e32 = (const int*)edge;
            if (m == 4) {
                int4 rr = *(const int4*)(e32 + base);
                int4 cc = *(const int4*)(e32 + e + base);
                r[0]=rr.x; r[1]=rr.y; r[2]=rr.z; r[3]=rr.w;
                c[0]=cc.x; c[1]=cc.y; c[2]=cc.z; c[3]=cc.w;
            } else {
                for (int k = 0; k < m; k++) { r[k]=e32[base+k]; c[k]=e32[e+base+k]; }
            }
        }
        #pragma unroll
        for (int k = 0; k < 4; k++) {
            if (k >= m) break;
            int rr = r[k], cc = c[k];
            if ((unsigned)rr >= (unsigned)n || (unsigned)cc >= (unsigned)n) { rr = 0; cc = 0; }
            g_rc[base + k] = make_int2(rr, cc);
            red_add_1(&g_deg[cc]);
        }
    } else {
        // ---- matvec: y0 = x @ W.T, 16 lanes per node, float4 loads ----
        __shared__ float4 sW[2 * DD / 4];
        int t = threadIdx.x;
        if (t < 2 * DD / 4) sW[t] = ((const float4*)W)[t];
        __syncthreads();
        int node = (((int)blockIdx.x - gc) * blockDim.x + t) >> 4;
        int l = t & 15;
        if (node >= n) return;
        float4 xv = ((const float4*)(x + (size_t)node * DD))[l];
        float4 w0 = sW[l];
        float4 w1 = sW[DD / 4 + l];
        float s0 = xv.x * w0.x + xv.y * w0.y + xv.z * w0.z + xv.w * w0.w;
        float s1 = xv.x * w1.x + xv.y * w1.y + xv.z * w1.z + xv.w * w1.w;
        #pragma unroll
        for (int o = 8; o; o >>= 1) {
            s0 += __shfl_xor_sync(0xffffffffu, s0, o);
            s1 += __shfl_xor_sync(0xffffffffu, s1, o);
        }
        if (l == 0) g_y0[node] = make_float2(s0, s1);
    }
}

// scale: d = rsqrt(deg+1); z0 = d*y0; a1 = (z0, d^2, d); t2 = 0; deg -> 0
__global__ void k_scale(int n) {
    int i = blockIdx.x * blockDim.x + threadIdx.x;
    if (i >= n) return;
    float d = rsqrtf((float)(g_deg[i] + 1));
    g_deg[i] = 0;
    float2 y = __ldg(&g_y0[i]);
    float2 z = make_float2(d * y.x, d * y.y);
    g_z0[i] = z;
    g_a1[i] = make_float4(z.x, z.y, d * d, d);
    g_t2[i] = make_float2(0.f, 0.f);
}

// hop 1 (edges only, 2/thread): a1.xy[c] += z0[r]
__global__ void k_edge1(int e) {
    int i2 = blockIdx.x * blockDim.x + threadIdx.x;
    int base = i2 * 2;
    if (base >= e) return;
    if (base + 1 < e) {
        int4 p = *(const int4*)&g_rc[base];   // (r0,c0,r1,c1)
        float2 v0 = __ldg(&g_z0[p.x]);
        float2 v1 = __ldg(&g_z0[p.z]);
        red_add_f2((float2*)&g_a1[p.y], v0.x, v0.y);
        red_add_f2((float2*)&g_a1[p.w], v1.x, v1.y);
    } else {
        int2 rc = g_rc[base];
        float2 v = __ldg(&g_z0[rc.x]);
        red_add_f2((float2*)&g_a1[rc.y], v.x, v.y);
    }
}

// hop 2 (edges only, 2/thread): t2[c] += d2[r]*t1[r]
__global__ void k_edge2(int e) {
    int i2 = blockIdx.x * blockDim.x + threadIdx.x;
    int base = i2 * 2;
    if (base >= e) return;
    if (base + 1 < e) {
        int4 p = *(const int4*)&g_rc[base];
        float4 a0 = __ldg(&g_a1[p.x]);
        float4 a1v = __ldg(&g_a1[p.z]);
        red_add_f2(&g_t2[p.y], a0.z * a0.x, a0.z * a0.y);
        red_add_f2(&g_t2[p.w], a1v.z * a1v.x, a1v.z * a1v.y);
    } else {
        int2 rc = g_rc[base];
        float4 a = __ldg(&g_a1[rc.x]);
        red_add_f2(&g_t2[rc.y], a.z * a.x, a.z * a.y);
    }
}

// out = log_softmax(dinv * (t2 + d^2 * t1) + b); hop-2 self term folded in.
// Fast-math MUFU exp/log (error ~2^-21, far below the 1e-3 tolerance).
__global__ void k_out(const float* __restrict__ b, float* __restrict__ out, int n) {
    int i = blockIdx.x * blockDim.x + threadIdx.x;
    if (i >= n) return;
    float4 a = g_a1[i];            // .xy = t1 final, .z = d^2, .w = dinv
    float2 t = g_t2[i];
    float l0 = a.w * (t.x + a.z * a.x) + b[0];
    float l1 = a.w * (t.y + a.z * a.y) + b[1];
    float m = fmaxf(l0, l1);
    float lse = m + __logf(__expf(l0 - m) + __expf(l1 - m));
    st_cs_f2((float2*)(out + 2 * i), make_float2(l0 - lse, l1 - lse));
}

// ---------------- launch ----------------

extern "C" void kernel_launch(void* const* d_in, const int* in_sizes, int n_in,
                              void* d_out, int out_size) {
    const float* x    = (const float*)d_in[0];
    const void*  edge = d_in[1];
    const float* W    = (const float*)d_in[2];
    const float* b    = (const float*)d_in[3];
    float*       out  = (float*)d_out;

    int n = in_sizes[0] / DD;   // 100000
    int e = in_sizes[1] / 2;    // 1600000

    const int T = 256;
    int gn  = (n + T - 1) / T;
    int gc  = ((e + 3) / 4 + T - 1) / T;
    int ge2 = ((e + 1) / 2 + T - 1) / T;
    int gw  = ((size_t)n * 16 + T - 1) / T;   // 16 lanes per node

    k_count_mv<<<gc + gw, T>>>(edge, x, W, e, n, gc);
    k_scale<<<gn, T>>>(n);
    k_edge1<<<ge2, T>>>(e);
    k_edge2<<<ge2, T>>>(e);
    k_out<<<gn, T>>>(b, out, n);
}